// round 16
// baseline (speedup 1.0000x reference)
#include <cuda_runtime.h>
#include <cuda_fp16.h>
#include <cstdint>

// ============================================================================
// out[8192,4096] = x @ W + b via 2:4 sparse tensor cores (mma.sp, conv c1).
// R16: gemm_sp epilogue -> smem-transposed coalesced RMW; corr -> R14 shape +
// packed (k,v) + half2 (2 m/thread); compact spread over 128 blocks.
// Mainloop identical to R14/R15 (validated, rel_err 2.985e-4).
// ============================================================================

static constexpr int MDIM = 8192, NDIM = 4096, KDIM = 4096;
static constexpr int NK = 64;
static constexpr int NTILES = (NDIM / 128) * (MDIM / 256);   // 1024
static constexpr int STAGES = 4;
static constexpr uint32_t ST_META = 8192, ST_B = 9216, STRIDE = 43008;
static constexpr uint32_t EPI_OFF = STAGES * STRIDE;              // 172032
static constexpr uint32_t SMEM_BYTES = 1024u + EPI_OFF + 256u * 36u * 4u; // 209920

__device__ __align__(128) __half g_xh[(size_t)MDIM * KDIM];        // x fp16 [m][k]
__device__ __align__(128) __half g_xt[(size_t)KDIM * MDIM];        // x fp16 [k][m]
__device__ __align__(128) __half g_wc[(size_t)NDIM * (KDIM / 2)];  // Wc [n][k/2]
__device__ __align__(16) uint32_t g_meta[(size_t)(NDIM / 16) * 128 * 16];
__device__ int    g_stc[128 * NDIM];
__device__ int    g_strk[512 * NDIM];
__device__ float  g_strv[512 * NDIM];
__device__ float2 g_rkv[32 * NDIM];          // packed {k_as_float, v} [slot][n]
__device__ int    g_rcnt[NDIM];

__device__ __forceinline__ uint32_t smem_u32(const void* p) {
    uint32_t a;
    asm("{ .reg .u64 t; cvta.to.shared.u64 t, %1; cvt.u32.u64 %0, t; }" : "=r"(a) : "l"(p));
    return a;
}
__device__ __forceinline__ uint32_t sw128(uint32_t off) {
    return off ^ ((off >> 3) & 0x70u);
}
__device__ __forceinline__ void cp16(uint32_t s, const void* g) {
    asm volatile("cp.async.cg.shared.global [%0], [%1], 16;" :: "r"(s), "l"(g));
}
__device__ __forceinline__ void ldsm4(uint32_t& r0, uint32_t& r1, uint32_t& r2, uint32_t& r3,
                                      uint32_t addr) {
    asm volatile("ldmatrix.sync.aligned.m8n8.x4.shared.b16 {%0,%1,%2,%3}, [%4];"
                 : "=r"(r0), "=r"(r1), "=r"(r2), "=r"(r3) : "r"(addr));
}
__device__ __forceinline__ void mma_sp(float* c, const uint32_t* a,
                                       uint32_t b0, uint32_t b1, uint32_t b2, uint32_t b3,
                                       uint32_t e) {
    asm volatile(
        "mma.sp::ordered_metadata.sync.aligned.m16n8k32.row.col.f32.f16.f16.f32 "
        "{%0,%1,%2,%3}, {%4,%5,%6,%7}, {%8,%9,%10,%11}, {%0,%1,%2,%3}, %12, 0x0;"
        : "+f"(c[0]), "+f"(c[1]), "+f"(c[2]), "+f"(c[3])
        : "r"(a[0]), "r"(a[1]), "r"(a[2]), "r"(a[3]),
          "r"(b0), "r"(b1), "r"(b2), "r"(b3), "r"(e));
}

// ---------------------------------------------------------------------------
__global__ void __launch_bounds__(256) cvt_x_kernel(const float* __restrict__ x) {
    __shared__ __half tile[64][66];
    const int bm = blockIdx.x >> 6;
    const int bk = blockIdx.x & 63;
    const int m0 = bm * 64, k0 = bk * 64;
    const int tc = threadIdx.x & 63, tr = threadIdx.x >> 6;
    #pragma unroll
    for (int r = 0; r < 16; r++) {
        const int mm = tr + r * 4;
        __half h = __float2half(x[(size_t)(m0 + mm) * KDIM + k0 + tc]);
        g_xh[(size_t)(m0 + mm) * KDIM + k0 + tc] = h;
        tile[tc][mm] = h;
    }
    __syncthreads();
    #pragma unroll
    for (int r = 0; r < 16; r++) {
        const int kk = tr + r * 4;
        g_xt[(size_t)(k0 + kk) * MDIM + m0 + tc] = tile[kk][tc];
    }
}

// ---------------------------------------------------------------------------
__global__ void __launch_bounds__(256) compressA_kernel(const float* __restrict__ w) {
    const int lane = threadIdx.x & 31;
    const int gsub = threadIdx.x >> 5;
    const int nb = blockIdx.x & 127;
    const int gc = blockIdx.x >> 7;
    const int n = nb * 32 + lane;
    const int G = gc * 8 + gsub;

    int rk_loc[4];
    float rv_loc[4];
    int cnt = 0;
    uint32_t m32 = 0, cv[8];

    #pragma unroll
    for (int g4 = 0; g4 < 8; g4++) {
        const int kb = G * 32 + g4 * 4;
        float vv[4];
        #pragma unroll
        for (int i = 0; i < 4; i++) vv[i] = w[(size_t)(kb + i) * NDIM + n];
        int i0 = -1, i1 = -1;
        float a0 = 0.0f, a1 = 0.0f;
        #pragma unroll
        for (int i = 0; i < 4; i++) {
            if (vv[i] != 0.0f) {
                if (i0 < 0)      { i0 = i; a0 = vv[i]; }
                else if (i1 < 0) { i1 = i; a1 = vv[i]; }
                else if (cnt < 4) { rk_loc[cnt] = kb + i; rv_loc[cnt] = vv[i]; cnt++; }
            }
        }
        if (i0 < 0) { i0 = 0; i1 = 1; }
        else if (i1 < 0) {
            if (i0 == 0) { i1 = 1; a1 = 0.0f; }
            else { i1 = i0; a1 = a0; i0 = 0; a0 = 0.0f; }
        }
        __half2 h = __floats2half2_rn(a0, a1);
        cv[g4] = *(uint32_t*)&h;
        m32 |= (uint32_t)(i0 | (i1 << 2)) << (g4 * 4);
    }
    uint4* wp = (uint4*)(g_wc + (size_t)n * (KDIM / 2) + (size_t)G * 16);
    wp[0] = make_uint4(cv[0], cv[1], cv[2], cv[3]);
    wp[1] = make_uint4(cv[4], cv[5], cv[6], cv[7]);
    uint32_t h0 = m32 & 0xFFFFu, h1 = m32 >> 16;
    uint32_t p0 = __shfl_xor_sync(0xffffffffu, h0, 8);
    uint32_t p1 = __shfl_xor_sync(0xffffffffu, h1, 8);
    if ((n & 8) == 0) {
        const size_t idx = (((size_t)(n >> 4) * 128 + G) * 8 + (n & 7)) * 2;
        g_meta[idx]     = h0 | (p0 << 16);
        g_meta[idx + 1] = h1 | (p1 << 16);
    }
    g_stc[G * NDIM + n] = cnt;
    #pragma unroll
    for (int j = 0; j < 4; j++) {
        const bool u = j < cnt;
        g_strk[(G * 4 + j) * NDIM + n] = u ? rk_loc[j] : 0;
        g_strv[(G * 4 + j) * NDIM + n] = u ? rv_loc[j] : 0.0f;
    }
}

// Per-n compaction into packed (k,v) pairs. 128 blocks x 32 threads.
__global__ void __launch_bounds__(32) compact_kernel() {
    const int n = blockIdx.x * 32 + threadIdx.x;
    int c = 0;
    #pragma unroll 1
    for (int G = 0; G < 128; G++) {
        const int cc = g_stc[G * NDIM + n];
        #pragma unroll 1
        for (int j = 0; j < cc; j++) {
            if (c < 32) {
                g_rkv[c * NDIM + n] = make_float2(
                    __int_as_float(g_strk[(G * 4 + j) * NDIM + n]),
                    g_strv[(G * 4 + j) * NDIM + n]);
                c++;
            }
        }
    }
    g_rcnt[n] = c;
}

// ---------------------------------------------------------------------------
// corr: out[m][n] = bias[n] + sum residuals. 2 m per thread (half2 gathers).
// grid = (MDIM/512) x (NDIM/32) = 16 x 128.
// ---------------------------------------------------------------------------
__global__ void __launch_bounds__(256)
corr_kernel(const float* __restrict__ bias, float* __restrict__ out) {
    const int bm = blockIdx.x >> 7;
    const int bn = blockIdx.x & 127;
    const int m = bm * 512 + threadIdx.x * 2;
    const int n0 = bn * 32;
    float* o0 = out + (size_t)m * NDIM + n0;
    float* o1 = o0 + NDIM;
    #pragma unroll 1
    for (int ch = 0; ch < 8; ch++) {
        const float4 bv = *(const float4*)(bias + n0 + ch * 4);
        float a0[4] = {bv.x, bv.y, bv.z, bv.w};
        float a1[4] = {bv.x, bv.y, bv.z, bv.w};
        #pragma unroll
        for (int cn = 0; cn < 4; cn++) {
            const int n = n0 + ch * 4 + cn;
            const int cnt = g_rcnt[n];
            #pragma unroll 1
            for (int j = 0; j < cnt; j++) {
                const float2 kv = g_rkv[j * NDIM + n];
                const int k = __float_as_int(kv.x);
                const __half2 x2 = *(const __half2*)(g_xt + (size_t)k * MDIM + m);
                const float2 xf = __half22float2(x2);
                a0[cn] += kv.y * xf.x;
                a1[cn] += kv.y * xf.y;
            }
        }
        *(float4*)(o0 + ch * 4) = make_float4(a0[0], a0[1], a0[2], a0[3]);
        *(float4*)(o1 + ch * 4) = make_float4(a1[0], a1[1], a1[2], a1[3]);
    }
}

// ---------------------------------------------------------------------------
// Sparse GEMM: mainloop identical to R14/R15; epilogue = smem transpose.
// ---------------------------------------------------------------------------
__device__ __forceinline__ void load_a(uint32_t st, const char* wc, int slab, int q) {
    int row = q >> 2, c = q & 3;
    cp16(st + sw128((uint32_t)(row * 64 + c * 16)),
         wc + (size_t)row * 4096 + (size_t)slab * 64 + c * 16);
}
__device__ __forceinline__ void load_m(uint32_t st, const char* mb, int slab, int q) {
    cp16(st + ST_META + (uint32_t)q * 16,
         mb + (size_t)(q >> 3) * 8192 + (size_t)slab * 128 + (q & 7) * 16);
}
__device__ __forceinline__ void load_b(uint32_t st, const char* xb, int slab, int q) {
    int row = q >> 3, c = q & 7;
    cp16(st + ST_B + sw128((uint32_t)(row * 128 + c * 16)),
         xb + (size_t)row * 8192 + (size_t)slab * 128 + c * 16);
}
__device__ __forceinline__ void tile_ptrs(int t, const char*& a, const char*& mp,
                                          const char*& b) {
    const int tn = t & 31, tm = t >> 5;
    a  = ((const char*)g_wc)   + (size_t)tn * 128 * 4096;
    mp = ((const char*)g_meta) + (size_t)tn * 8 * 8192;
    b  = ((const char*)g_xh)   + (size_t)tm * 256 * 8192;
}
__device__ __forceinline__ void load_a_frag(uint32_t sb, uint32_t a_off0, int g,
                                            uint32_t m_woff, uint32_t (&af)[4][4],
                                            uint32_t (&mt)[4]) {
    #pragma unroll
    for (int t = 0; t < 4; t++) {
        ldsm4(af[t][0], af[t][1], af[t][2], af[t][3],
              sb + sw128(a_off0 + (uint32_t)(t * 1024 + g * 32)));
        asm volatile("ld.shared.u32 %0, [%1];" : "=r"(mt[t])
                     : "r"(sb + ST_META + m_woff + (uint32_t)(t * 128 + g * 64)));
    }
}
__device__ __forceinline__ void load_b_frag(uint32_t sb, int wm, int brow, uint32_t b_col0,
                                            int g, int q, uint32_t (&bq)[8]) {
    const int mh = q >> 1, mg = q & 1;
    const uint32_t rb = (uint32_t)((wm * 64 + mh * 32 + mg * 16 + brow) * 128 + g * 64)
                        + b_col0;
    ldsm4(bq[0], bq[1], bq[2], bq[3], sb + ST_B + sw128(rb));
    ldsm4(bq[4], bq[5], bq[6], bq[7], sb + ST_B + sw128(rb + 32));
}

__global__ void __launch_bounds__(256, 1)
gemm_sp_kernel(float* __restrict__ out) {
    extern __shared__ char smem_raw[];
    const uint32_t S0 = (smem_u32(smem_raw) + 1023u) & ~1023u;
    char* sbase = smem_raw + (S0 - smem_u32(smem_raw));
    float* epi = (float*)(sbase + EPI_OFF);

    const int tid  = threadIdx.x;
    const int lane = tid & 31;
    const int wn   = (tid >> 5) & 1;
    const int wm   = tid >> 6;
    const int bid  = blockIdx.x;
    const int gdim = gridDim.x;

    const int rq = lane >> 2;
    const uint32_t a_off0 = (uint32_t)((wn * 64 + (lane & 15)) * 64 + ((lane >> 4) << 4));
    const int brow = ((lane >> 4) << 3) + (lane & 7);
    const uint32_t b_col0 = (uint32_t)(((lane >> 3) & 1) << 4);
    const uint32_t m_woff = (uint32_t)((wn * 4) * 128 + (rq * 2 + (lane & 1)) * 4);

    float acc[4][8][4];
    #pragma unroll
    for (int t = 0; t < 4; t++)
        #pragma unroll
        for (int j = 0; j < 8; j++)
            #pragma unroll
            for (int q = 0; q < 4; q++) acc[t][j][q] = 0.0f;

    {
        const char *pa, *pm, *px;
        tile_ptrs(bid, pa, pm, px);
        #pragma unroll
        for (int p = 0; p < STAGES - 1; p++) {
            const uint32_t st = S0 + (uint32_t)p * STRIDE;
            load_a(st, pa, p, tid); load_a(st, pa, p, tid + 256);
            if (tid < 64) load_m(st, pm, p, tid);
            #pragma unroll
            for (int r = 0; r < 8; r++) load_b(st, px, p, tid + (r << 8));
            asm volatile("cp.async.commit_group;" ::: "memory");
        }
    }
    asm volatile("cp.async.wait_group 1;" ::: "memory");
    __syncthreads();

    uint32_t af[2][4][4], mt[2][4], bq[2][8];
    load_a_frag(S0, a_off0, 0, m_woff, af[0], mt[0]);
    load_b_frag(S0, wm, brow, b_col0, 0, 0, bq[0]);

    for (int t_idx = bid; t_idx < NTILES; t_idx += gdim) {
        const char *aC, *mC, *xC, *aN, *mN, *xN;
        tile_ptrs(t_idx, aC, mC, xC);
        const bool hasNext = (t_idx + gdim) < NTILES;
        tile_ptrs(hasNext ? (t_idx + gdim) : t_idx, aN, mN, xN);
        const char* aNm = aN - (size_t)NK * 64;
        const char* mNm = mN - (size_t)NK * 128;
        const char* xNm = xN - (size_t)NK * 128;
        const bool lastTile = !hasNext;

        for (int it = 0; it < NK; ++it) {
            const uint32_t sb = S0 + (uint32_t)(it & 3) * STRIDE;
            const uint32_t stNext = S0 + (uint32_t)((it + 1) & 3) * STRIDE;
            const bool last = lastTile && (it == NK - 1);
            const int j = it + (STAGES - 1);
            const bool inT = j < NK;
            const bool dl = inT || hasNext;
            const uint32_t stJ = S0 + (uint32_t)(j & 3) * STRIDE;
            const char* pa = inT ? aC : aNm;
            const char* pm = inT ? mC : mNm;
            const char* px = inT ? xC : xNm;

            #pragma unroll
            for (int c = 0; c < 8; c++) {
                const int g = c >> 2, q = c & 3;
                const int cb = c & 1;
                if (c < 7)
                    load_b_frag(sb, wm, brow, b_col0, (c + 1) >> 2, (c + 1) & 3, bq[cb ^ 1]);
                else if (!last)
                    load_b_frag(stNext, wm, brow, b_col0, 0, 0, bq[cb ^ 1]);
                if (c == 3)
                    load_a_frag(sb, a_off0, 1, m_woff, af[1], mt[1]);
                else if (c == 7 && !last)
                    load_a_frag(stNext, a_off0, 0, m_woff, af[0], mt[0]);
                if (dl) {
                    if      (c == 0) { load_b(stJ, px, j, tid);        load_b(stJ, px, j, tid + 256);  }
                    else if (c == 1) { load_b(stJ, px, j, tid + 512);  load_b(stJ, px, j, tid + 768);  }
                    else if (c == 2) { load_b(stJ, px, j, tid + 1024); load_b(stJ, px, j, tid + 1280); }
                    else if (c == 3) { load_b(stJ, px, j, tid + 1536); load_b(stJ, px, j, tid + 1792); }
                    else if (c == 4) { load_a(stJ, pa, j, tid); }
                    else if (c == 5) { load_a(stJ, pa, j, tid + 256); }
                    else if (c == 6) { if (tid < 64) load_m(stJ, pm, j, tid); }
                }
                const int jb = (q >> 1) * 4 + (q & 1) * 2;
                #pragma unroll
                for (int t = 0; t < 4; t++) {
                    mma_sp(acc[t][jb],     af[g][t], bq[cb][0], bq[cb][1], bq[cb][4], bq[cb][5], mt[g][t]);
                    mma_sp(acc[t][jb + 1], af[g][t], bq[cb][2], bq[cb][3], bq[cb][6], bq[cb][7], mt[g][t]);
                }
            }
            asm volatile("cp.async.commit_group;" ::: "memory");
            if (!last) {
                asm volatile("cp.async.wait_group 1;" ::: "memory");
                __syncthreads();
            }
        }

        // Epilogue: smem transpose -> coalesced RMW.  4 rounds of 32n x 256m.
        {
            const int tile_n0 = (t_idx & 31) * 128;
            const int tile_m0 = (t_idx >> 5) * 256;
            const int mi = (lane & 3) * 2;
            #pragma unroll 1
            for (int t = 0; t < 4; t++) {
                // scatter acc -> epi[m_local][n_local], stride 36 (conflict-free)
                #pragma unroll
                for (int j = 0; j < 8; j++) {
                    const int ml = wm * 64 + j * 8 + mi;
                    const int nl = wn * 16 + rq;
                    epi[ml * 36 + nl]            = acc[t][j][0];
                    epi[(ml + 1) * 36 + nl]      = acc[t][j][1];
                    epi[ml * 36 + nl + 8]        = acc[t][j][2];
                    epi[(ml + 1) * 36 + nl + 8]  = acc[t][j][3];
                    acc[t][j][0] = 0.0f; acc[t][j][1] = 0.0f;
                    acc[t][j][2] = 0.0f; acc[t][j][3] = 0.0f;
                }
                __syncthreads();
                // coalesced RMW: warp-per-row, lane = n within round
                const int ngl = tile_n0 + ((lane < 16) ? (t * 16 + lane)
                                                       : (64 + t * 16 + (lane - 16)));
                const int ww = tid >> 5;
                #pragma unroll
                for (int i = 0; i < 32; i++) {
                    const int row = ww + i * 8;
                    float* po = out + (size_t)(tile_m0 + row) * NDIM + ngl;
                    *po += epi[row * 36 + lane];
                }
                __syncthreads();
            }
        }
    }
}

// ---------------------------------------------------------------------------
extern "C" void kernel_launch(void* const* d_in, const int* in_sizes, int n_in,
                              void* d_out, int out_size) {
    (void)in_sizes; (void)n_in; (void)out_size;
    const float* x = (const float*)d_in[0];
    const float* w = (const float*)d_in[1];
    const float* b = (const float*)d_in[2];
    float* out = (float*)d_out;

    cvt_x_kernel<<<128 * 64, 256>>>(x);
    compressA_kernel<<<128 * 16, 256>>>(w);
    compact_kernel<<<128, 32>>>();
    corr_kernel<<<16 * 128, 256>>>(b, out);

    int sms = 0;
    cudaDeviceGetAttribute(&sms, cudaDevAttrMultiProcessorCount, 0);
    if (sms <= 0) sms = 148;
    const int grid = sms < NTILES ? sms : NTILES;

    cudaFuncSetAttribute(gemm_sp_kernel, cudaFuncAttributeMaxDynamicSharedMemorySize,
                         (int)SMEM_BYTES);
    gemm_sp_kernel<<<grid, 256, SMEM_BYTES>>>(out);
}

// round 17
// speedup vs baseline: 4.3767x; 4.3767x over previous
#include <cuda_runtime.h>
#include <cuda_fp16.h>
#include <cstdint>

// ============================================================================
// out[8192,4096] = x @ W + b via 2:4 sparse tensor cores (mma.sp, conv c1).
// R17: fix R16's acc spill (#pragma unroll 1 -> full unroll on epilogue);
//      corr v4 with smem-resident residual metadata. Mainloop unchanged.
// ============================================================================

static constexpr int MDIM = 8192, NDIM = 4096, KDIM = 4096;
static constexpr int NK = 64;
static constexpr int NTILES = (NDIM / 128) * (MDIM / 256);   // 1024
static constexpr int STAGES = 4;
static constexpr uint32_t ST_META = 8192, ST_B = 9216, STRIDE = 43008;
static constexpr uint32_t EPI_OFF = STAGES * STRIDE;              // 172032
static constexpr uint32_t SMEM_BYTES = 1024u + EPI_OFF + 256u * 36u * 4u; // 209920

__device__ __align__(128) __half g_xh[(size_t)MDIM * KDIM];        // x fp16 [m][k]
__device__ __align__(128) __half g_xt[(size_t)KDIM * MDIM];        // x fp16 [k][m]
__device__ __align__(128) __half g_wc[(size_t)NDIM * (KDIM / 2)];  // Wc [n][k/2]
__device__ __align__(16) uint32_t g_meta[(size_t)(NDIM / 16) * 128 * 16];
__device__ int    g_stc[128 * NDIM];
__device__ int    g_strk[512 * NDIM];
__device__ float  g_strv[512 * NDIM];
__device__ float2 g_rkv[32 * NDIM];          // packed {k_as_float, v} [slot][n]
__device__ int    g_rcnt[NDIM];

__device__ __forceinline__ uint32_t smem_u32(const void* p) {
    uint32_t a;
    asm("{ .reg .u64 t; cvta.to.shared.u64 t, %1; cvt.u32.u64 %0, t; }" : "=r"(a) : "l"(p));
    return a;
}
__device__ __forceinline__ uint32_t sw128(uint32_t off) {
    return off ^ ((off >> 3) & 0x70u);
}
__device__ __forceinline__ void cp16(uint32_t s, const void* g) {
    asm volatile("cp.async.cg.shared.global [%0], [%1], 16;" :: "r"(s), "l"(g));
}
__device__ __forceinline__ void ldsm4(uint32_t& r0, uint32_t& r1, uint32_t& r2, uint32_t& r3,
                                      uint32_t addr) {
    asm volatile("ldmatrix.sync.aligned.m8n8.x4.shared.b16 {%0,%1,%2,%3}, [%4];"
                 : "=r"(r0), "=r"(r1), "=r"(r2), "=r"(r3) : "r"(addr));
}
__device__ __forceinline__ void mma_sp(float* c, const uint32_t* a,
                                       uint32_t b0, uint32_t b1, uint32_t b2, uint32_t b3,
                                       uint32_t e) {
    asm volatile(
        "mma.sp::ordered_metadata.sync.aligned.m16n8k32.row.col.f32.f16.f16.f32 "
        "{%0,%1,%2,%3}, {%4,%5,%6,%7}, {%8,%9,%10,%11}, {%0,%1,%2,%3}, %12, 0x0;"
        : "+f"(c[0]), "+f"(c[1]), "+f"(c[2]), "+f"(c[3])
        : "r"(a[0]), "r"(a[1]), "r"(a[2]), "r"(a[3]),
          "r"(b0), "r"(b1), "r"(b2), "r"(b3), "r"(e));
}

// ---------------------------------------------------------------------------
__global__ void __launch_bounds__(256) cvt_x_kernel(const float* __restrict__ x) {
    __shared__ __half tile[64][66];
    const int bm = blockIdx.x >> 6;
    const int bk = blockIdx.x & 63;
    const int m0 = bm * 64, k0 = bk * 64;
    const int tc = threadIdx.x & 63, tr = threadIdx.x >> 6;
    #pragma unroll
    for (int r = 0; r < 16; r++) {
        const int mm = tr + r * 4;
        __half h = __float2half(x[(size_t)(m0 + mm) * KDIM + k0 + tc]);
        g_xh[(size_t)(m0 + mm) * KDIM + k0 + tc] = h;
        tile[tc][mm] = h;
    }
    __syncthreads();
    #pragma unroll
    for (int r = 0; r < 16; r++) {
        const int kk = tr + r * 4;
        g_xt[(size_t)(k0 + kk) * MDIM + m0 + tc] = tile[kk][tc];
    }
}

// ---------------------------------------------------------------------------
__global__ void __launch_bounds__(256) compressA_kernel(const float* __restrict__ w) {
    const int lane = threadIdx.x & 31;
    const int gsub = threadIdx.x >> 5;
    const int nb = blockIdx.x & 127;
    const int gc = blockIdx.x >> 7;
    const int n = nb * 32 + lane;
    const int G = gc * 8 + gsub;

    int rk_loc[4];
    float rv_loc[4];
    int cnt = 0;
    uint32_t m32 = 0, cv[8];

    #pragma unroll
    for (int g4 = 0; g4 < 8; g4++) {
        const int kb = G * 32 + g4 * 4;
        float vv[4];
        #pragma unroll
        for (int i = 0; i < 4; i++) vv[i] = w[(size_t)(kb + i) * NDIM + n];
        int i0 = -1, i1 = -1;
        float a0 = 0.0f, a1 = 0.0f;
        #pragma unroll
        for (int i = 0; i < 4; i++) {
            if (vv[i] != 0.0f) {
                if (i0 < 0)      { i0 = i; a0 = vv[i]; }
                else if (i1 < 0) { i1 = i; a1 = vv[i]; }
                else if (cnt < 4) { rk_loc[cnt] = kb + i; rv_loc[cnt] = vv[i]; cnt++; }
            }
        }
        if (i0 < 0) { i0 = 0; i1 = 1; }
        else if (i1 < 0) {
            if (i0 == 0) { i1 = 1; a1 = 0.0f; }
            else { i1 = i0; a1 = a0; i0 = 0; a0 = 0.0f; }
        }
        __half2 h = __floats2half2_rn(a0, a1);
        cv[g4] = *(uint32_t*)&h;
        m32 |= (uint32_t)(i0 | (i1 << 2)) << (g4 * 4);
    }
    uint4* wp = (uint4*)(g_wc + (size_t)n * (KDIM / 2) + (size_t)G * 16);
    wp[0] = make_uint4(cv[0], cv[1], cv[2], cv[3]);
    wp[1] = make_uint4(cv[4], cv[5], cv[6], cv[7]);
    uint32_t h0 = m32 & 0xFFFFu, h1 = m32 >> 16;
    uint32_t p0 = __shfl_xor_sync(0xffffffffu, h0, 8);
    uint32_t p1 = __shfl_xor_sync(0xffffffffu, h1, 8);
    if ((n & 8) == 0) {
        const size_t idx = (((size_t)(n >> 4) * 128 + G) * 8 + (n & 7)) * 2;
        g_meta[idx]     = h0 | (p0 << 16);
        g_meta[idx + 1] = h1 | (p1 << 16);
    }
    g_stc[G * NDIM + n] = cnt;
    #pragma unroll
    for (int j = 0; j < 4; j++) {
        const bool u = j < cnt;
        g_strk[(G * 4 + j) * NDIM + n] = u ? rk_loc[j] : 0;
        g_strv[(G * 4 + j) * NDIM + n] = u ? rv_loc[j] : 0.0f;
    }
}

// Per-n compaction into packed (k,v) pairs. 128 blocks x 32 threads.
__global__ void __launch_bounds__(32) compact_kernel() {
    const int n = blockIdx.x * 32 + threadIdx.x;
    int c = 0;
    #pragma unroll 1
    for (int G = 0; G < 128; G++) {
        const int cc = g_stc[G * NDIM + n];
        #pragma unroll 1
        for (int j = 0; j < cc; j++) {
            if (c < 32) {
                g_rkv[c * NDIM + n] = make_float2(
                    __int_as_float(g_strk[(G * 4 + j) * NDIM + n]),
                    g_strv[(G * 4 + j) * NDIM + n]);
                c++;
            }
        }
    }
    g_rcnt[n] = c;
}

// ---------------------------------------------------------------------------
// corr v4: smem-resident residual metadata; 2 m per thread (half2 gathers).
// grid = (MDIM/512) x (NDIM/32) = 16 x 128.
// ---------------------------------------------------------------------------
__global__ void __launch_bounds__(256)
corr_kernel(const float* __restrict__ bias, float* __restrict__ out) {
    __shared__ float2 skv[32][32];   // [n_local][slot]
    __shared__ int scnt[32];
    const int bm = blockIdx.x >> 7;
    const int bn = blockIdx.x & 127;
    const int n0 = bn * 32;

    if (threadIdx.x < 32) scnt[threadIdx.x] = g_rcnt[n0 + threadIdx.x];
    {
        const int nl = threadIdx.x & 31;
        const int s0 = threadIdx.x >> 5;   // 0..7
        #pragma unroll
        for (int it = 0; it < 4; it++) {
            const int slot = it * 8 + s0;
            skv[nl][slot] = g_rkv[slot * NDIM + n0 + nl];
        }
    }
    __syncthreads();

    const int m = bm * 512 + threadIdx.x * 2;
    float* o0 = out + (size_t)m * NDIM + n0;
    float* o1 = o0 + NDIM;
    #pragma unroll 1
    for (int ch = 0; ch < 8; ch++) {
        const float4 bv = *(const float4*)(bias + n0 + ch * 4);
        float a0[4] = {bv.x, bv.y, bv.z, bv.w};
        float a1[4] = {bv.x, bv.y, bv.z, bv.w};
        #pragma unroll
        for (int cn = 0; cn < 4; cn++) {
            const int nl = ch * 4 + cn;
            const int cnt = scnt[nl];
            #pragma unroll 1
            for (int j = 0; j < cnt; j++) {
                const float2 kv = skv[nl][j];
                const int k = __float_as_int(kv.x);
                const __half2 x2 = *(const __half2*)(g_xt + (size_t)k * MDIM + m);
                const float2 xf = __half22float2(x2);
                a0[cn] += kv.y * xf.x;
                a1[cn] += kv.y * xf.y;
            }
        }
        *(float4*)(o0 + ch * 4) = make_float4(a0[0], a0[1], a0[2], a0[3]);
        *(float4*)(o1 + ch * 4) = make_float4(a1[0], a1[1], a1[2], a1[3]);
    }
}

// ---------------------------------------------------------------------------
// Sparse GEMM: mainloop identical; epilogue smem-transpose, FULLY UNROLLED.
// ---------------------------------------------------------------------------
__device__ __forceinline__ void load_a(uint32_t st, const char* wc, int slab, int q) {
    int row = q >> 2, c = q & 3;
    cp16(st + sw128((uint32_t)(row * 64 + c * 16)),
         wc + (size_t)row * 4096 + (size_t)slab * 64 + c * 16);
}
__device__ __forceinline__ void load_m(uint32_t st, const char* mb, int slab, int q) {
    cp16(st + ST_META + (uint32_t)q * 16,
         mb + (size_t)(q >> 3) * 8192 + (size_t)slab * 128 + (q & 7) * 16);
}
__device__ __forceinline__ void load_b(uint32_t st, const char* xb, int slab, int q) {
    int row = q >> 3, c = q & 7;
    cp16(st + ST_B + sw128((uint32_t)(row * 128 + c * 16)),
         xb + (size_t)row * 8192 + (size_t)slab * 128 + c * 16);
}
__device__ __forceinline__ void tile_ptrs(int t, const char*& a, const char*& mp,
                                          const char*& b) {
    const int tn = t & 31, tm = t >> 5;
    a  = ((const char*)g_wc)   + (size_t)tn * 128 * 4096;
    mp = ((const char*)g_meta) + (size_t)tn * 8 * 8192;
    b  = ((const char*)g_xh)   + (size_t)tm * 256 * 8192;
}
__device__ __forceinline__ void load_a_frag(uint32_t sb, uint32_t a_off0, int g,
                                            uint32_t m_woff, uint32_t (&af)[4][4],
                                            uint32_t (&mt)[4]) {
    #pragma unroll
    for (int t = 0; t < 4; t++) {
        ldsm4(af[t][0], af[t][1], af[t][2], af[t][3],
              sb + sw128(a_off0 + (uint32_t)(t * 1024 + g * 32)));
        asm volatile("ld.shared.u32 %0, [%1];" : "=r"(mt[t])
                     : "r"(sb + ST_META + m_woff + (uint32_t)(t * 128 + g * 64)));
    }
}
__device__ __forceinline__ void load_b_frag(uint32_t sb, int wm, int brow, uint32_t b_col0,
                                            int g, int q, uint32_t (&bq)[8]) {
    const int mh = q >> 1, mg = q & 1;
    const uint32_t rb = (uint32_t)((wm * 64 + mh * 32 + mg * 16 + brow) * 128 + g * 64)
                        + b_col0;
    ldsm4(bq[0], bq[1], bq[2], bq[3], sb + ST_B + sw128(rb));
    ldsm4(bq[4], bq[5], bq[6], bq[7], sb + ST_B + sw128(rb + 32));
}

__global__ void __launch_bounds__(256, 1)
gemm_sp_kernel(float* __restrict__ out) {
    extern __shared__ char smem_raw[];
    const uint32_t S0 = (smem_u32(smem_raw) + 1023u) & ~1023u;
    char* sbase = smem_raw + (S0 - smem_u32(smem_raw));
    float* epi = (float*)(sbase + EPI_OFF);

    const int tid  = threadIdx.x;
    const int lane = tid & 31;
    const int wn   = (tid >> 5) & 1;
    const int wm   = tid >> 6;
    const int bid  = blockIdx.x;
    const int gdim = gridDim.x;

    const int rq = lane >> 2;
    const uint32_t a_off0 = (uint32_t)((wn * 64 + (lane & 15)) * 64 + ((lane >> 4) << 4));
    const int brow = ((lane >> 4) << 3) + (lane & 7);
    const uint32_t b_col0 = (uint32_t)(((lane >> 3) & 1) << 4);
    const uint32_t m_woff = (uint32_t)((wn * 4) * 128 + (rq * 2 + (lane & 1)) * 4);

    float acc[4][8][4];
    #pragma unroll
    for (int t = 0; t < 4; t++)
        #pragma unroll
        for (int j = 0; j < 8; j++)
            #pragma unroll
            for (int q = 0; q < 4; q++) acc[t][j][q] = 0.0f;

    {
        const char *pa, *pm, *px;
        tile_ptrs(bid, pa, pm, px);
        #pragma unroll
        for (int p = 0; p < STAGES - 1; p++) {
            const uint32_t st = S0 + (uint32_t)p * STRIDE;
            load_a(st, pa, p, tid); load_a(st, pa, p, tid + 256);
            if (tid < 64) load_m(st, pm, p, tid);
            #pragma unroll
            for (int r = 0; r < 8; r++) load_b(st, px, p, tid + (r << 8));
            asm volatile("cp.async.commit_group;" ::: "memory");
        }
    }
    asm volatile("cp.async.wait_group 1;" ::: "memory");
    __syncthreads();

    uint32_t af[2][4][4], mt[2][4], bq[2][8];
    load_a_frag(S0, a_off0, 0, m_woff, af[0], mt[0]);
    load_b_frag(S0, wm, brow, b_col0, 0, 0, bq[0]);

    for (int t_idx = bid; t_idx < NTILES; t_idx += gdim) {
        const char *aC, *mC, *xC, *aN, *mN, *xN;
        tile_ptrs(t_idx, aC, mC, xC);
        const bool hasNext = (t_idx + gdim) < NTILES;
        tile_ptrs(hasNext ? (t_idx + gdim) : t_idx, aN, mN, xN);
        const char* aNm = aN - (size_t)NK * 64;
        const char* mNm = mN - (size_t)NK * 128;
        const char* xNm = xN - (size_t)NK * 128;
        const bool lastTile = !hasNext;

        for (int it = 0; it < NK; ++it) {
            const uint32_t sb = S0 + (uint32_t)(it & 3) * STRIDE;
            const uint32_t stNext = S0 + (uint32_t)((it + 1) & 3) * STRIDE;
            const bool last = lastTile && (it == NK - 1);
            const int j = it + (STAGES - 1);
            const bool inT = j < NK;
            const bool dl = inT || hasNext;
            const uint32_t stJ = S0 + (uint32_t)(j & 3) * STRIDE;
            const char* pa = inT ? aC : aNm;
            const char* pm = inT ? mC : mNm;
            const char* px = inT ? xC : xNm;

            #pragma unroll
            for (int c = 0; c < 8; c++) {
                const int g = c >> 2, q = c & 3;
                const int cb = c & 1;
                if (c < 7)
                    load_b_frag(sb, wm, brow, b_col0, (c + 1) >> 2, (c + 1) & 3, bq[cb ^ 1]);
                else if (!last)
                    load_b_frag(stNext, wm, brow, b_col0, 0, 0, bq[cb ^ 1]);
                if (c == 3)
                    load_a_frag(sb, a_off0, 1, m_woff, af[1], mt[1]);
                else if (c == 7 && !last)
                    load_a_frag(stNext, a_off0, 0, m_woff, af[0], mt[0]);
                if (dl) {
                    if      (c == 0) { load_b(stJ, px, j, tid);        load_b(stJ, px, j, tid + 256);  }
                    else if (c == 1) { load_b(stJ, px, j, tid + 512);  load_b(stJ, px, j, tid + 768);  }
                    else if (c == 2) { load_b(stJ, px, j, tid + 1024); load_b(stJ, px, j, tid + 1280); }
                    else if (c == 3) { load_b(stJ, px, j, tid + 1536); load_b(stJ, px, j, tid + 1792); }
                    else if (c == 4) { load_a(stJ, pa, j, tid); }
                    else if (c == 5) { load_a(stJ, pa, j, tid + 256); }
                    else if (c == 6) { if (tid < 64) load_m(stJ, pm, j, tid); }
                }
                const int jb = (q >> 1) * 4 + (q & 1) * 2;
                #pragma unroll
                for (int t = 0; t < 4; t++) {
                    mma_sp(acc[t][jb],     af[g][t], bq[cb][0], bq[cb][1], bq[cb][4], bq[cb][5], mt[g][t]);
                    mma_sp(acc[t][jb + 1], af[g][t], bq[cb][2], bq[cb][3], bq[cb][6], bq[cb][7], mt[g][t]);
                }
            }
            asm volatile("cp.async.commit_group;" ::: "memory");
            if (!last) {
                asm volatile("cp.async.wait_group 1;" ::: "memory");
                __syncthreads();
            }
        }

        // Epilogue: smem transpose -> coalesced RMW. FULLY UNROLLED (no spill).
        {
            const int tile_n0 = (t_idx & 31) * 128;
            const int tile_m0 = (t_idx >> 5) * 256;
            const int mi = (lane & 3) * 2;
            const int ww = tid >> 5;
            #pragma unroll
            for (int t = 0; t < 4; t++) {
                #pragma unroll
                for (int j = 0; j < 8; j++) {
                    const int ml = wm * 64 + j * 8 + mi;
                    const int nl = wn * 16 + rq;
                    epi[ml * 36 + nl]            = acc[t][j][0];
                    epi[(ml + 1) * 36 + nl]      = acc[t][j][1];
                    epi[ml * 36 + nl + 8]        = acc[t][j][2];
                    epi[(ml + 1) * 36 + nl + 8]  = acc[t][j][3];
                    acc[t][j][0] = 0.0f; acc[t][j][1] = 0.0f;
                    acc[t][j][2] = 0.0f; acc[t][j][3] = 0.0f;
                }
                __syncthreads();
                const int ngl = tile_n0 + ((lane < 16) ? (t * 16 + lane)
                                                       : (64 + t * 16 + (lane - 16)));
                #pragma unroll
                for (int i = 0; i < 32; i++) {
                    const int row = ww + i * 8;
                    float* po = out + (size_t)(tile_m0 + row) * NDIM + ngl;
                    *po += epi[row * 36 + lane];
                }
                __syncthreads();
            }
        }
    }
}

// ---------------------------------------------------------------------------
extern "C" void kernel_launch(void* const* d_in, const int* in_sizes, int n_in,
                              void* d_out, int out_size) {
    (void)in_sizes; (void)n_in; (void)out_size;
    const float* x = (const float*)d_in[0];
    const float* w = (const float*)d_in[1];
    const float* b = (const float*)d_in[2];
    float* out = (float*)d_out;

    cvt_x_kernel<<<128 * 64, 256>>>(x);
    compressA_kernel<<<128 * 16, 256>>>(w);
    compact_kernel<<<128, 32>>>();
    corr_kernel<<<16 * 128, 256>>>(b, out);

    int sms = 0;
    cudaDeviceGetAttribute(&sms, cudaDevAttrMultiProcessorCount, 0);
    if (sms <= 0) sms = 148;
    const int grid = sms < NTILES ? sms : NTILES;

    cudaFuncSetAttribute(gemm_sp_kernel, cudaFuncAttributeMaxDynamicSharedMemorySize,
                         (int)SMEM_BYTES);
    gemm_sp_kernel<<<grid, 256, SMEM_BYTES>>>(out);
}